// round 8
// baseline (speedup 1.0000x reference)
#include <cuda_runtime.h>

#define BATCH 8
#define HH 2048
#define WW 2048
#define PATCH 16
#define DD 16
#define FEAT 256
#define NPIX (128 * 128)

typedef unsigned long long ull;
typedef unsigned int uint;

// ---------------- device scratch ----------------
__device__ float g_tc[256];
__device__ float g_ts[256];
__device__ float g_R[DD][FEAT];
__device__ float g_I[DD][FEAT];
__device__ __align__(16) float2 g_M[FEAT][DD / 2];   // M[f][k] pairs along k
__device__ float g_c[DD];
__device__ float g_img[BATCH * DD * NPIX];           // 8 MB [b][d][i][j]
__device__ float g_ps[512];                          // partials [bd*4+slice]
__device__ float g_pq[512];
__device__ int g_cnt[DD];                            // per-channel arrival counters

// ---------------- packed f32x2 helpers ----------------
__device__ __forceinline__ ull packf2(float lo, float hi) {
    ull r; asm("mov.b64 %0, {%1, %2};" : "=l"(r) : "f"(lo), "f"(hi)); return r;
}
__device__ __forceinline__ void fmaf2(ull& d, ull a, ull b) {
    asm("fma.rn.f32x2 %0, %1, %2, %0;" : "+l"(d) : "l"(a), "l"(b));
}
__device__ __forceinline__ ull addf2(ull a, ull b) {
    ull r; asm("add.rn.f32x2 %0, %1, %2;" : "=l"(r) : "l"(a), "l"(b)); return r;
}
__device__ __forceinline__ void unpackf2(ull v, float& lo, float& hi) {
    asm("mov.b64 {%0, %1}, %2;" : "=f"(lo), "=f"(hi) : "l"(v));
}
__device__ __forceinline__ void lds_v2u64(ull& a, ull& b, uint addr) {
    asm volatile("ld.shared.v2.u64 {%0, %1}, [%2];" : "=l"(a), "=l"(b) : "r"(addr));
}
__device__ __forceinline__ void pref_l2(const void* p) {
    asm volatile("prefetch.global.L2 [%0];" :: "l"(p));
}
__device__ __forceinline__ int ld_acq(const int* p) {
    int v; asm volatile("ld.acquire.gpu.b32 %0, [%1];" : "=r"(v) : "l"(p)); return v;
}

// ---------------- K1: table + R[j,f], I[j,f] ----------------
__global__ void k_prep1(const float* __restrict__ Wr, const float* __restrict__ Wi) {
    __shared__ float sc[256], ss[256], wr[256], wi[256];
    int f = threadIdx.x, j = blockIdx.x;
    float s, c;
    sincospif((float)f * (1.0f / 128.0f), &s, &c);
    sc[f] = c; ss[f] = s;
    if (j == 0) { g_tc[f] = c; g_ts[f] = s; }
    wr[f] = Wr[j * FEAT + f]; wi[f] = Wi[j * FEAT + f];
    __syncthreads();
    float R = 0.f, I = 0.f;
    for (int d = 0; d < 256; ++d) {
        int t = (d * f) & 255;
        float cc = sc[t], s2 = ss[t];
        R += wr[d] * cc + wi[d] * s2;
        I += wi[d] * cc - wr[d] * s2;
    }
    g_R[j][f] = R; g_I[j][f] = I;
}

// ---------------- K2: M[f,k], c[k]; also reset counters ----------------
__global__ void k_prep2(const float* __restrict__ br, const float* __restrict__ bi) {
    int e = blockIdx.x * 256 + threadIdx.x;
    int f = e >> 4, k = e & 15;
    float m = 0.f;
    for (int j = 0; j < DD; ++j) {
        int t = (16 * j * k) & 255;
        m += g_R[j][f] * g_tc[t] - g_I[j][f] * g_ts[t];
    }
    ((float*)g_M)[f * DD + k] = m * (1.0f / 16.0f);
    if (e < DD) {
        float cc = 0.f;
        for (int j = 0; j < DD; ++j) {
            int t = (16 * j * e) & 255;
            cc += (br[j] - bi[j]) * g_tc[t] - (br[j] + bi[j]) * g_ts[t];
        }
        g_c[e] = cc * (1.0f / 16.0f);
        g_cnt[e] = 0;
    }
}

// ---------------- K3: main patch GEMM, warp = 32 adjacent patches -------------
// 4 streams of 8 patches, ALL 16 k per warp (acc[4][8] = 64 regs).
// lane l: a = l>>2 (patch sub-index), q = l&3 (s2 quad).
// Per s1: 4 coalesced LDG.128 (L2-prefetched 4 rows ahead, no reg dbuf),
// 16 swizzled broadcast LDS.128 feed 128 FMA2 (8:1 ratio). 5 blocks/SM.
__global__ void __launch_bounds__(128, 5) k_main(const float* __restrict__ x) {
    __shared__ uint4 sM[FEAT * 4];   // row f: unit m stored at col (m+(f>>2))&3
    __shared__ float scc[DD];
    int tid = threadIdx.x;
    int lane = tid & 31;
    int warp = tid >> 5;
    int u = blockIdx.x * 4 + warp;          // 4096 warp units
    int b = u >> 9;
    int r = u & 511;
    int ph = r >> 2;                        // patch row
    int seg = r & 3;                        // 32-patch column segment
    int a = lane >> 2;
    int q = lane & 3;

    const float* base = x + (size_t)b * HH * WW + (size_t)(ph * PATCH) * WW + seg * 512;

    // warm L2 for the first rows while staging M
#pragma unroll
    for (int rr = 0; rr < 4; ++rr)
        pref_l2(base + (size_t)rr * WW + (lane & 15) * 32);

    {
        const uint4* gm = (const uint4*)g_M;
        for (int f = tid; f < 256; f += 128)
#pragma unroll
            for (int m = 0; m < 4; ++m)
                sM[f * 4 + ((m + (f >> 2)) & 3)] = gm[f * 4 + m];
        if (tid < DD) scc[tid] = g_c[tid];
    }
    __syncthreads();

    uint sMaddr = (uint)__cvta_generic_to_shared(sM);

    ull acc[4][8];
    ull z = packf2(0.f, 0.f);
#pragma unroll
    for (int t = 0; t < 4; ++t)
#pragma unroll
        for (int k2 = 0; k2 < 8; ++k2) acc[t][k2] = z;

#pragma unroll 1
    for (int s1 = 0; s1 < PATCH; ++s1) {
        if (s1 < 12) pref_l2(base + (size_t)(s1 + 4) * WW + (lane & 15) * 32);
        const float4* rp = (const float4*)(base + (size_t)s1 * WW);
        float4 cur[4];
#pragma unroll
        for (int t = 0; t < 4; ++t) cur[t] = rp[t * 32 + lane];

        uint rowbase = sMaddr + (uint)(s1 * 16 + q * 4) * 64;
#pragma unroll
        for (int e = 0; e < 4; ++e) {
            uint ra = rowbase + (uint)e * 64;
            ull vp[4];
#pragma unroll
            for (int t = 0; t < 4; ++t) {
                float xv = (e == 0) ? cur[t].x : (e == 1) ? cur[t].y
                         : (e == 2) ? cur[t].z : cur[t].w;
                vp[t] = packf2(xv, xv);
            }
            // half A: k-pairs 0..3
            {
                ull mk[4];
                lds_v2u64(mk[0], mk[1], ra + (uint)(((0 + q) & 3) << 4));
                lds_v2u64(mk[2], mk[3], ra + (uint)(((1 + q) & 3) << 4));
#pragma unroll
                for (int t = 0; t < 4; ++t)
#pragma unroll
                    for (int k2 = 0; k2 < 4; ++k2) fmaf2(acc[t][k2], vp[t], mk[k2]);
            }
            // half B: k-pairs 4..7
            {
                ull mk[4];
                lds_v2u64(mk[0], mk[1], ra + (uint)(((2 + q) & 3) << 4));
                lds_v2u64(mk[2], mk[3], ra + (uint)(((3 + q) & 3) << 4));
#pragma unroll
                for (int t = 0; t < 4; ++t)
#pragma unroll
                    for (int k2 = 0; k2 < 4; ++k2) fmaf2(acc[t][k2 + 4], vp[t], mk[k2]);
            }
        }
    }

    // reduce-scatter over quad lanes: round1 xor1, round2 xor2
    int kb = ((q & 1) << 2) | (q & 2);
#pragma unroll
    for (int t = 0; t < 4; ++t) {
        ull tmp[4], fin[2];
#pragma unroll
        for (int j = 0; j < 4; ++j) {
            ull send = (q & 1) ? acc[t][j] : acc[t][j + 4];
            ull keep = (q & 1) ? acc[t][j + 4] : acc[t][j];
            tmp[j] = addf2(keep, __shfl_xor_sync(0xffffffffu, send, 1));
        }
#pragma unroll
        for (int j = 0; j < 2; ++j) {
            ull send = (q & 2) ? tmp[j] : tmp[j + 2];
            ull keep = (q & 2) ? tmp[j + 2] : tmp[j];
            fin[j] = addf2(keep, __shfl_xor_sync(0xffffffffu, send, 2));
        }
        int col = seg * 32 + t * 8 + a;
        float* gp = g_img + (size_t)b * DD * NPIX + ph * 128 + col;
#pragma unroll
        for (int j = 0; j < 2; ++j) {
            int k0 = 2 * (kb + j);
            ull v = addf2(fin[j], packf2(scc[k0], scc[k0 + 1]));
            float lo, hi;
            unpackf2(v, lo, hi);
            gp[(size_t)k0 * NPIX] = lo;
            gp[(size_t)(k0 + 1) * NPIX] = hi;
        }
    }
}

// ---------------- float4 + shfl rolling 3x3 conv ----------------
__device__ __forceinline__ void conv_rows(float4 v, int lane, const float* w,
                                          float4& h0, float4& h1, float4& h2) {
    float l = __shfl_up_sync(0xffffffffu, v.w, 1);
    float rr = __shfl_down_sync(0xffffffffu, v.x, 1);
    if (lane == 0) l = 0.f;
    if (lane == 31) rr = 0.f;
    float lx = l, ly = v.x, lz = v.y, lw = v.z;
    float rx = v.y, ry = v.z, rz = v.w, rw = rr;
#define HROW(H, W0, W1, W2)                                   \
    H.x = W0 * lx + W1 * v.x + W2 * rx;                       \
    H.y = W0 * ly + W1 * v.y + W2 * ry;                       \
    H.z = W0 * lz + W1 * v.z + W2 * rz;                       \
    H.w = W0 * lw + W1 * v.w + W2 * rw;
    HROW(h0, w[0], w[1], w[2])
    HROW(h1, w[3], w[4], w[5])
    HROW(h2, w[6], w[7], w[8])
#undef HROW
}

__device__ __forceinline__ float4 ld_row(const float* __restrict__ base, int r, int lane) {
    if ((unsigned)r < 128u) return ((const float4*)(base + r * 128))[lane];
    return make_float4(0.f, 0.f, 0.f, 0.f);
}

// ---------------- K4: fused conv + stats + grid-sync + BN + write -------------
// 512 blocks x 256 threads; block = 32 rows of one (b,d) image; warp = 4 rows.
__global__ void __launch_bounds__(256) k_fused(const float* __restrict__ cw,
                                               const float* __restrict__ cb,
                                               const float* __restrict__ gamma,
                                               const float* __restrict__ beta,
                                               float* __restrict__ out) {
    int blk = blockIdx.x;            // bd*4 + slice
    int bd = blk >> 2;
    int d = bd & 15;
    int slice = blk & 3;
    int tid = threadIdx.x;
    int lane = tid & 31, wp = tid >> 5;
    int r0 = slice * 32 + wp * 4;
    float w[9];
#pragma unroll
    for (int t = 0; t < 9; ++t) w[t] = cw[d * 9 + t];
    float bias = cb[d];
    const float* base = g_img + (size_t)bd * NPIX;

    float4 A = make_float4(0, 0, 0, 0), B = make_float4(0, 0, 0, 0);
    float4 cv[4];
    float s = 0.f, sq = 0.f;
#pragma unroll
    for (int r = r0 - 1; r <= r0 + 4; ++r) {
        float4 v = ld_row(base, r, lane);
        float4 h0, h1, h2;
        conv_rows(v, lane, w, h0, h1, h2);
        if (r >= r0 + 1) {
            float4 o;
            o.x = A.x + h2.x + bias;
            o.y = A.y + h2.y + bias;
            o.z = A.z + h2.z + bias;
            o.w = A.w + h2.w + bias;
            cv[r - 1 - r0] = o;
            s += o.x + o.y + o.z + o.w;
            sq += o.x * o.x + o.y * o.y + o.z * o.z + o.w * o.w;
        }
        A.x = B.x + h1.x; A.y = B.y + h1.y; A.z = B.z + h1.z; A.w = B.w + h1.w;
        B = h0;
    }
#pragma unroll
    for (int off = 16; off; off >>= 1) {
        s += __shfl_down_sync(0xffffffffu, s, off);
        sq += __shfl_down_sync(0xffffffffu, sq, off);
    }
    __shared__ float rs[8], rq[8];
    if (lane == 0) { rs[wp] = s; rq[wp] = sq; }
    __syncthreads();
    if (tid == 0) {
        float ts = 0.f, tq = 0.f;
#pragma unroll
        for (int i = 0; i < 8; ++i) { ts += rs[i]; tq += rq[i]; }
        g_ps[blk] = ts;
        g_pq[blk] = tq;
        __threadfence();                       // release partials
        atomicAdd(&g_cnt[d], 1);
        while (ld_acq(&g_cnt[d]) < 32) {}      // acquire-load spin
    }
    __syncthreads();

    // deterministic re-reduce of this channel's 32 partials (L2 loads, fixed order)
    __shared__ float sp[32], sq2[32];
    __shared__ float smu, ssc;
    if (tid < 32) {
        int bb = tid >> 2, sl = tid & 3;
        int idx = ((bb * DD + d) << 2) + sl;
        sp[tid] = __ldcg(&g_ps[idx]);
        sq2[tid] = __ldcg(&g_pq[idx]);
        __syncwarp();
        if (tid == 0) {
            float S = 0.f, Q = 0.f;
#pragma unroll
            for (int i = 0; i < 32; ++i) { S += sp[i]; Q += sq2[i]; }
            float n = 131072.0f;
            float mu = S / n;
            float var = Q / n - mu * mu;
            smu = mu;
            ssc = rsqrtf(var + 1e-5f) * gamma[d];
        }
    }
    __syncthreads();
    float mu = smu, sc = ssc, bt = beta[d];

    float4* op = (float4*)(out + (size_t)bd * NPIX) + lane;
#pragma unroll
    for (int ri = 0; ri < 4; ++ri) {
        float4 o;
        o.x = (cv[ri].x - mu) * sc + bt;
        o.y = (cv[ri].y - mu) * sc + bt;
        o.z = (cv[ri].z - mu) * sc + bt;
        o.w = (cv[ri].w - mu) * sc + bt;
        op[(r0 + ri) * 32] = o;
    }
}

extern "C" void kernel_launch(void* const* d_in, const int* in_sizes, int n_in,
                              void* d_out, int out_size) {
    const float* x = (const float*)d_in[0];
    const float* Wr = (const float*)d_in[1];
    const float* br = (const float*)d_in[2];
    const float* Wi = (const float*)d_in[3];
    const float* bi = (const float*)d_in[4];
    const float* cw = (const float*)d_in[5];
    const float* cb = (const float*)d_in[6];
    const float* gamma = (const float*)d_in[7];
    const float* beta = (const float*)d_in[8];
    float* out = (float*)d_out;

    k_prep1<<<16, 256>>>(Wr, Wi);
    k_prep2<<<16, 256>>>(br, bi);
    k_main<<<1024, 128>>>(x);
    k_fused<<<512, 256>>>(cw, cb, gamma, beta, out);
}

// round 9
// speedup vs baseline: 1.0939x; 1.0939x over previous
#include <cuda_runtime.h>

#define BATCH 8
#define HH 2048
#define WW 2048
#define PATCH 16
#define DD 16
#define FEAT 256
#define NPIX (128 * 128)

typedef unsigned long long ull;
typedef unsigned int uint;

// ---------------- device scratch ----------------
__device__ float g_tc[256];
__device__ float g_ts[256];
__device__ float g_R[DD][FEAT];
__device__ float g_I[DD][FEAT];
__device__ __align__(16) float2 g_M[FEAT][DD / 2];   // M[f][k] pairs along k
__device__ float g_c[DD];
__device__ float g_img[BATCH * DD * NPIX];           // 8 MB [b][d][i][j]
__device__ float g_ps[512];                          // partials [bd*4+slice]
__device__ float g_pq[512];
__device__ int g_cnt[DD];                            // per-channel arrival counters

// ---------------- packed f32x2 helpers ----------------
__device__ __forceinline__ ull packf2(float lo, float hi) {
    ull r; asm("mov.b64 %0, {%1, %2};" : "=l"(r) : "f"(lo), "f"(hi)); return r;
}
__device__ __forceinline__ void fmaf2(ull& d, ull a, ull b) {
    asm("fma.rn.f32x2 %0, %1, %2, %0;" : "+l"(d) : "l"(a), "l"(b));
}
__device__ __forceinline__ ull addf2(ull a, ull b) {
    ull r; asm("add.rn.f32x2 %0, %1, %2;" : "=l"(r) : "l"(a), "l"(b)); return r;
}
__device__ __forceinline__ void unpackf2(ull v, float& lo, float& hi) {
    asm("mov.b64 {%0, %1}, %2;" : "=f"(lo), "=f"(hi) : "l"(v));
}
__device__ __forceinline__ void lds_v2u64(ull& a, ull& b, uint addr) {
    asm volatile("ld.shared.v2.u64 {%0, %1}, [%2];" : "=l"(a), "=l"(b) : "r"(addr));
}
__device__ __forceinline__ int ld_acq(const int* p) {
    int v; asm volatile("ld.acquire.gpu.b32 %0, [%1];" : "=r"(v) : "l"(p)); return v;
}

// ---------------- K1: table + R[j,f], I[j,f] ----------------
__global__ void k_prep1(const float* __restrict__ Wr, const float* __restrict__ Wi) {
    __shared__ float sc[256], ss[256], wr[256], wi[256];
    int f = threadIdx.x, j = blockIdx.x;
    float s, c;
    sincospif((float)f * (1.0f / 128.0f), &s, &c);
    sc[f] = c; ss[f] = s;
    if (j == 0) { g_tc[f] = c; g_ts[f] = s; }
    wr[f] = Wr[j * FEAT + f]; wi[f] = Wi[j * FEAT + f];
    __syncthreads();
    float R = 0.f, I = 0.f;
    for (int d = 0; d < 256; ++d) {
        int t = (d * f) & 255;
        float cc = sc[t], s2 = ss[t];
        R += wr[d] * cc + wi[d] * s2;
        I += wi[d] * cc - wr[d] * s2;
    }
    g_R[j][f] = R; g_I[j][f] = I;
}

// ---------------- K2: M[f,k], c[k]; also reset counters ----------------
__global__ void k_prep2(const float* __restrict__ br, const float* __restrict__ bi) {
    int e = blockIdx.x * 256 + threadIdx.x;
    int f = e >> 4, k = e & 15;
    float m = 0.f;
    for (int j = 0; j < DD; ++j) {
        int t = (16 * j * k) & 255;
        m += g_R[j][f] * g_tc[t] - g_I[j][f] * g_ts[t];
    }
    ((float*)g_M)[f * DD + k] = m * (1.0f / 16.0f);
    if (e < DD) {
        float cc = 0.f;
        for (int j = 0; j < DD; ++j) {
            int t = (16 * j * e) & 255;
            cc += (br[j] - bi[j]) * g_tc[t] - (br[j] + bi[j]) * g_ts[t];
        }
        g_c[e] = cc * (1.0f / 16.0f);
        g_cnt[e] = 0;
    }
}

// ---------------- K3: main patch GEMM (round-3 proven config) ----------------
// Warp = 32 adjacent patches (4 streams of 8), ALL 16 k (acc[4][8] = 64 regs),
// register double-buffer for the next x row. lane l: a=l>>2, q=l&3 (s2 quad).
// Per s1: 4 coalesced LDG.128, 16 swizzled broadcast LDS.128 feed 128 FMA2.
__global__ void __launch_bounds__(128, 4) k_main(const float* __restrict__ x) {
    __shared__ uint4 sM[FEAT * 4];   // row f: unit m stored at col (m+(f>>2))&3
    __shared__ float scc[DD];
    int tid = threadIdx.x;
    {
        const uint4* gm = (const uint4*)g_M;
        for (int f = tid; f < 256; f += 128)
#pragma unroll
            for (int m = 0; m < 4; ++m)
                sM[f * 4 + ((m + (f >> 2)) & 3)] = gm[f * 4 + m];
        if (tid < DD) scc[tid] = g_c[tid];
    }
    __syncthreads();

    uint sMaddr = (uint)__cvta_generic_to_shared(sM);
    int lane = tid & 31;
    int warp = tid >> 5;
    int u = blockIdx.x * 4 + warp;          // 4096 warp units
    int b = u >> 9;
    int r = u & 511;
    int ph = r >> 2;                        // patch row
    int seg = r & 3;                        // 32-patch column segment
    int a = lane >> 2;
    int q = lane & 3;

    const float* base = x + (size_t)b * HH * WW + (size_t)(ph * PATCH) * WW + seg * 512;

    ull acc[4][8];
    ull z = packf2(0.f, 0.f);
#pragma unroll
    for (int t = 0; t < 4; ++t)
#pragma unroll
        for (int k2 = 0; k2 < 8; ++k2) acc[t][k2] = z;

    const float4* rp = (const float4*)base;
    float4 cur[4];
#pragma unroll
    for (int t = 0; t < 4; ++t) cur[t] = rp[t * 32 + lane];

#pragma unroll 1
    for (int s1 = 0; s1 < PATCH; ++s1) {
        float4 nxt[4];
        if (s1 < 15) {
            const float4* rn = (const float4*)(base + (size_t)(s1 + 1) * WW);
#pragma unroll
            for (int t = 0; t < 4; ++t) nxt[t] = rn[t * 32 + lane];
        }
        uint rowbase = sMaddr + (uint)(s1 * 16 + q * 4) * 64;
#pragma unroll
        for (int e = 0; e < 4; ++e) {
            uint ra = rowbase + (uint)e * 64;
            ull vp[4];
#pragma unroll
            for (int t = 0; t < 4; ++t) {
                float xv = (e == 0) ? cur[t].x : (e == 1) ? cur[t].y
                         : (e == 2) ? cur[t].z : cur[t].w;
                vp[t] = packf2(xv, xv);
            }
            // half A: k-pairs 0..3
            {
                ull mk[4];
                lds_v2u64(mk[0], mk[1], ra + (uint)(((0 + q) & 3) << 4));
                lds_v2u64(mk[2], mk[3], ra + (uint)(((1 + q) & 3) << 4));
#pragma unroll
                for (int t = 0; t < 4; ++t)
#pragma unroll
                    for (int k2 = 0; k2 < 4; ++k2) fmaf2(acc[t][k2], vp[t], mk[k2]);
            }
            // half B: k-pairs 4..7
            {
                ull mk[4];
                lds_v2u64(mk[0], mk[1], ra + (uint)(((2 + q) & 3) << 4));
                lds_v2u64(mk[2], mk[3], ra + (uint)(((3 + q) & 3) << 4));
#pragma unroll
                for (int t = 0; t < 4; ++t)
#pragma unroll
                    for (int k2 = 0; k2 < 4; ++k2) fmaf2(acc[t][k2 + 4], vp[t], mk[k2]);
            }
        }
        if (s1 < 15) {
#pragma unroll
            for (int t = 0; t < 4; ++t) cur[t] = nxt[t];
        }
    }

    // reduce-scatter over quad lanes: round1 xor1, round2 xor2
    int kb = ((q & 1) << 2) | (q & 2);
#pragma unroll
    for (int t = 0; t < 4; ++t) {
        ull tmp[4], fin[2];
#pragma unroll
        for (int j = 0; j < 4; ++j) {
            ull send = (q & 1) ? acc[t][j] : acc[t][j + 4];
            ull keep = (q & 1) ? acc[t][j + 4] : acc[t][j];
            tmp[j] = addf2(keep, __shfl_xor_sync(0xffffffffu, send, 1));
        }
#pragma unroll
        for (int j = 0; j < 2; ++j) {
            ull send = (q & 2) ? tmp[j] : tmp[j + 2];
            ull keep = (q & 2) ? tmp[j + 2] : tmp[j];
            fin[j] = addf2(keep, __shfl_xor_sync(0xffffffffu, send, 2));
        }
        int col = seg * 32 + t * 8 + a;
        float* gp = g_img + (size_t)b * DD * NPIX + ph * 128 + col;
#pragma unroll
        for (int j = 0; j < 2; ++j) {
            int k0 = 2 * (kb + j);
            ull v = addf2(fin[j], packf2(scc[k0], scc[k0 + 1]));
            float lo, hi;
            unpackf2(v, lo, hi);
            gp[(size_t)k0 * NPIX] = lo;
            gp[(size_t)(k0 + 1) * NPIX] = hi;
        }
    }
}

// ---------------- float4 + shfl rolling 3x3 conv ----------------
__device__ __forceinline__ void conv_rows(float4 v, int lane, const float* w,
                                          float4& h0, float4& h1, float4& h2) {
    float l = __shfl_up_sync(0xffffffffu, v.w, 1);
    float rr = __shfl_down_sync(0xffffffffu, v.x, 1);
    if (lane == 0) l = 0.f;
    if (lane == 31) rr = 0.f;
    float lx = l, ly = v.x, lz = v.y, lw = v.z;
    float rx = v.y, ry = v.z, rz = v.w, rw = rr;
#define HROW(H, W0, W1, W2)                                   \
    H.x = W0 * lx + W1 * v.x + W2 * rx;                       \
    H.y = W0 * ly + W1 * v.y + W2 * ry;                       \
    H.z = W0 * lz + W1 * v.z + W2 * rz;                       \
    H.w = W0 * lw + W1 * v.w + W2 * rw;
    HROW(h0, w[0], w[1], w[2])
    HROW(h1, w[3], w[4], w[5])
    HROW(h2, w[6], w[7], w[8])
#undef HROW
}

__device__ __forceinline__ float4 ld_row(const float* __restrict__ base, int r, int lane) {
    if ((unsigned)r < 128u) return ((const float4*)(base + r * 128))[lane];
    return make_float4(0.f, 0.f, 0.f, 0.f);
}

// ---------------- K4: fused conv + stats + grid-sync + BN + write -------------
// 512 blocks x 256 threads; block = 32 rows of one (b,d) image; warp = 4 rows.
__global__ void __launch_bounds__(256) k_fused(const float* __restrict__ cw,
                                               const float* __restrict__ cb,
                                               const float* __restrict__ gamma,
                                               const float* __restrict__ beta,
                                               float* __restrict__ out) {
    int blk = blockIdx.x;            // bd*4 + slice
    int bd = blk >> 2;
    int d = bd & 15;
    int slice = blk & 3;
    int tid = threadIdx.x;
    int lane = tid & 31, wp = tid >> 5;
    int r0 = slice * 32 + wp * 4;
    float w[9];
#pragma unroll
    for (int t = 0; t < 9; ++t) w[t] = cw[d * 9 + t];
    float bias = cb[d];
    const float* base = g_img + (size_t)bd * NPIX;

    float4 A = make_float4(0, 0, 0, 0), B = make_float4(0, 0, 0, 0);
    float4 cv[4];
    float s = 0.f, sq = 0.f;
#pragma unroll
    for (int r = r0 - 1; r <= r0 + 4; ++r) {
        float4 v = ld_row(base, r, lane);
        float4 h0, h1, h2;
        conv_rows(v, lane, w, h0, h1, h2);
        if (r >= r0 + 1) {
            float4 o;
            o.x = A.x + h2.x + bias;
            o.y = A.y + h2.y + bias;
            o.z = A.z + h2.z + bias;
            o.w = A.w + h2.w + bias;
            cv[r - 1 - r0] = o;
            s += o.x + o.y + o.z + o.w;
            sq += o.x * o.x + o.y * o.y + o.z * o.z + o.w * o.w;
        }
        A.x = B.x + h1.x; A.y = B.y + h1.y; A.z = B.z + h1.z; A.w = B.w + h1.w;
        B = h0;
    }
#pragma unroll
    for (int off = 16; off; off >>= 1) {
        s += __shfl_down_sync(0xffffffffu, s, off);
        sq += __shfl_down_sync(0xffffffffu, sq, off);
    }
    __shared__ float rs[8], rq[8];
    if (lane == 0) { rs[wp] = s; rq[wp] = sq; }
    __syncthreads();
    if (tid == 0) {
        float ts = 0.f, tq = 0.f;
#pragma unroll
        for (int i = 0; i < 8; ++i) { ts += rs[i]; tq += rq[i]; }
        g_ps[blk] = ts;
        g_pq[blk] = tq;
        __threadfence();                       // release partials
        atomicAdd(&g_cnt[d], 1);
        while (ld_acq(&g_cnt[d]) < 32) {}      // acquire-load spin
    }
    __syncthreads();

    // deterministic re-reduce of this channel's 32 partials (L2 loads, fixed order)
    __shared__ float sp[32], sq2[32];
    __shared__ float smu, ssc;
    if (tid < 32) {
        int bb = tid >> 2, sl = tid & 3;
        int idx = ((bb * DD + d) << 2) + sl;
        sp[tid] = __ldcg(&g_ps[idx]);
        sq2[tid] = __ldcg(&g_pq[idx]);
        __syncwarp();
        if (tid == 0) {
            float S = 0.f, Q = 0.f;
#pragma unroll
            for (int i = 0; i < 32; ++i) { S += sp[i]; Q += sq2[i]; }
            float n = 131072.0f;
            float mu = S / n;
            float var = Q / n - mu * mu;
            smu = mu;
            ssc = rsqrtf(var + 1e-5f) * gamma[d];
        }
    }
    __syncthreads();
    float mu = smu, sc = ssc, bt = beta[d];

    float4* op = (float4*)(out + (size_t)bd * NPIX) + lane;
#pragma unroll
    for (int ri = 0; ri < 4; ++ri) {
        float4 o;
        o.x = (cv[ri].x - mu) * sc + bt;
        o.y = (cv[ri].y - mu) * sc + bt;
        o.z = (cv[ri].z - mu) * sc + bt;
        o.w = (cv[ri].w - mu) * sc + bt;
        op[(r0 + ri) * 32] = o;
    }
}

extern "C" void kernel_launch(void* const* d_in, const int* in_sizes, int n_in,
                              void* d_out, int out_size) {
    const float* x = (const float*)d_in[0];
    const float* Wr = (const float*)d_in[1];
    const float* br = (const float*)d_in[2];
    const float* Wi = (const float*)d_in[3];
    const float* bi = (const float*)d_in[4];
    const float* cw = (const float*)d_in[5];
    const float* cb = (const float*)d_in[6];
    const float* gamma = (const float*)d_in[7];
    const float* beta = (const float*)d_in[8];
    float* out = (float*)d_out;

    k_prep1<<<16, 256>>>(Wr, Wi);
    k_prep2<<<16, 256>>>(br, bi);
    k_main<<<1024, 128>>>(x);
    k_fused<<<512, 256>>>(cw, cb, gamma, beta, out);
}